// round 11
// baseline (speedup 1.0000x reference)
#include <cuda_runtime.h>
#include <cuda_bf16.h>
#include <cuda_fp16.h>

#define N_NODES  100000
#define N_EDGES  3200000
#define N_GRAPHS 512
#define HID      16
#define LABELS   10
#define VOCAB    128

#define SCAN_BLK 1024
#define SCAN_NB  ((N_NODES + SCAN_BLK - 1) / SCAN_BLK)   // 98

// ---------------- scratch (device globals; no allocation allowed) ----------
__device__ int      g_deg   [N_NODES];
__device__ int      g_off   [N_NODES];
__device__ int      g_bsum  [SCAN_NB];
__device__ int      g_bbase [SCAN_NB];
__device__ unsigned g_combo [N_EDGES];      // (rank<<17) | dst
__device__ int2     g_csr2  [N_EDGES];      // {src, packed(dinv[src],x[src])} by dst
__device__ unsigned g_v     [N_NODES];      // packed: dinv (17-bit mant) | x (7 bits)
__device__ float    g_dinv  [N_NODES];
__device__ float4   g_h1    [N_NODES * 4];  // relu(layer1), f32
__device__ uint4    g_a2h   [N_NODES * 2];  // (h1 @ W2) * dinv[i], fp16 (32B/row)
__device__ float4   g_h2    [N_NODES * 4];  // relu(layer2), f32
__device__ float4   g_EW    [VOCAB * 4];    // emb @ W1   (128 x 16 = 8KB)
__device__ float    g_sums  [N_GRAPHS * HID];
__device__ float    g_cnt   [N_GRAPHS];

__device__ __forceinline__ void red4(float4* p, float a, float b, float c, float d) {
    asm volatile("red.global.add.v4.f32 [%0], {%1,%2,%3,%4};"
                 :: "l"(p), "f"(a), "f"(b), "f"(c), "f"(d) : "memory");
}
__device__ __forceinline__ unsigned pack2(float a, float b) {
    __half2 h = __floats2half2_rn(a, b);
    return *reinterpret_cast<unsigned*>(&h);
}
__device__ __forceinline__ float2 unpack2(unsigned u) {
    __half2 h = *reinterpret_cast<__half2*>(&u);
    return __half22float2(h);
}

// ---------------- build ------------------------------------------------------

__global__ __launch_bounds__(256) void k_init() {
    int i = blockIdx.x * blockDim.x + threadIdx.x;
    if (i < N_NODES) g_deg[i] = 0;
    if (i < N_GRAPHS * HID) g_sums[i] = 0.0f;
    if (i < N_GRAPHS) g_cnt[i] = 0.0f;
}

// degree histogram; the atomic's return value is the edge's rank in its bucket
__global__ __launch_bounds__(256) void k_deg_rank(const int* __restrict__ dst, int E) {
    int e = blockIdx.x * blockDim.x + threadIdx.x;
    if (e >= E) return;
    int d = dst[e];
    unsigned rank = (unsigned)atomicAdd(&g_deg[d], 1);
    g_combo[e] = (rank << 17) | (unsigned)d;
}

// shfl-based block scan (1024/block)
__global__ __launch_bounds__(SCAN_BLK) void k_scan1() {
    __shared__ int wtot[32];
    int gid = blockIdx.x * SCAN_BLK + threadIdx.x;
    int lane = threadIdx.x & 31, wid = threadIdx.x >> 5;
    int v = (gid < N_NODES) ? g_deg[gid] : 0;
    int x = v;
#pragma unroll
    for (int o = 1; o < 32; o <<= 1) {
        int t = __shfl_up_sync(0xffffffffu, x, o);
        if (lane >= o) x += t;
    }
    if (lane == 31) wtot[wid] = x;
    __syncthreads();
    if (threadIdx.x < 32) {
        int w = wtot[threadIdx.x];
        int y = w;
#pragma unroll
        for (int o = 1; o < 32; o <<= 1) {
            int t = __shfl_up_sync(0xffffffffu, y, o);
            if (threadIdx.x >= o) y += t;
        }
        wtot[threadIdx.x] = y - w;
        if (threadIdx.x == 31) g_bsum[blockIdx.x] = y;
    }
    __syncthreads();
    if (gid < N_NODES) g_off[gid] = x - v + wtot[wid];
}

// block 0: scan block totals; block 1: EW = emb @ W1
__global__ __launch_bounds__(128) void k_scan2_ew(const float* __restrict__ emb,
                                                  const float* __restrict__ W1) {
    int t = threadIdx.x;
    if (blockIdx.x == 0) {
        __shared__ int s[128];
        int v = (t < SCAN_NB) ? g_bsum[t] : 0;
        s[t] = v;
        __syncthreads();
#pragma unroll
        for (int off = 1; off < 128; off <<= 1) {
            int u = (t >= off) ? s[t - off] : 0;
            __syncthreads();
            s[t] += u;
            __syncthreads();
        }
        if (t < SCAN_NB) g_bbase[t] = s[t] - v;
    } else {
        __shared__ float sW[HID * HID];
        sW[t] = W1[t];
        sW[t + 128] = W1[t + 128];
        __syncthreads();
        float h[HID];
#pragma unroll
        for (int k = 0; k < HID; k++) h[k] = emb[t * HID + k];
#pragma unroll
        for (int q = 0; q < 4; q++) {
            float o[4];
#pragma unroll
            for (int jj = 0; jj < 4; jj++) {
                float s = 0.0f;
#pragma unroll
                for (int k = 0; k < HID; k++) s = fmaf(h[k], sW[k * HID + 4 * q + jj], s);
                o[jj] = s;
            }
            g_EW[t * 4 + q] = make_float4(o[0], o[1], o[2], o[3]);
        }
    }
}

// finalize offsets/dinv AND pack v = (dinv rounded to 17-bit mant) | x
__global__ __launch_bounds__(256) void k_scan3_v(const int* __restrict__ x) {
    int i = blockIdx.x * blockDim.x + threadIdx.x;
    if (i >= N_NODES) return;
    int o = g_off[i] + g_bbase[i >> 10];
    g_off[i] = o;
    float di = rsqrtf((float)g_deg[i] + 1.0f);
    g_dinv[i] = di;
    unsigned b = (__float_as_uint(di) + 0x40u) & ~0x7Fu;   // round-to-nearest at bit 7
    g_v[i] = b | (unsigned)x[i];
}

// scatter with NO atomics: pos = off[dst] + rank
__global__ __launch_bounds__(256) void k_scatter(const int* __restrict__ src, int E) {
    int e = blockIdx.x * blockDim.x + threadIdx.x;
    if (e >= E) return;
    int s = src[e];
    unsigned c = g_combo[e];
    int d = (int)(c & 0x1FFFFu);
    int pos = __ldg(&g_off[d]) + (int)(c >> 17);
    g_csr2[pos] = make_int2(s, (int)__ldg(&g_v[s]));
}

// ---------------- layer-1 gather: smem EW table, zero random loads ----------
__global__ __launch_bounds__(256) void k_gather1(const float* __restrict__ b1) {
    __shared__ float sEW[VOCAB * HID];        // 8KB
    const float* ew = (const float*)g_EW;
    for (int k = threadIdx.x; k < VOCAB * HID; k += 256) sEW[k] = ew[k];
    __syncthreads();

    int n = (blockIdx.x * blockDim.x + threadIdx.x) >> 5;
    if (n >= N_NODES) return;
    int lane = threadIdx.x & 31;
    int eq = lane >> 2, fj = lane & 3;
    int off = __ldg(&g_off[n]);
    int deg = __ldg(&g_deg[n]);

    float4 acc = make_float4(0.f, 0.f, 0.f, 0.f);
    for (int base = 0; base < deg; base += 8) {
        int e = base + eq;
        if (e < deg) {
            int2 c = __ldg(&g_csr2[off + e]);
            unsigned vb = (unsigned)c.y;
            int   xs = vb & 0x7Fu;
            float ds = __uint_as_float(vb & ~0x7Fu);
            float4 w = *(const float4*)&sEW[xs * HID + fj * 4];
            acc.x = fmaf(w.x, ds, acc.x);
            acc.y = fmaf(w.y, ds, acc.y);
            acc.z = fmaf(w.z, ds, acc.z);
            acc.w = fmaf(w.w, ds, acc.w);
        }
    }
#pragma unroll
    for (int o = 16; o >= 4; o >>= 1) {
        acc.x += __shfl_down_sync(0xffffffffu, acc.x, o);
        acc.y += __shfl_down_sync(0xffffffffu, acc.y, o);
        acc.z += __shfl_down_sync(0xffffffffu, acc.z, o);
        acc.w += __shfl_down_sync(0xffffffffu, acc.w, o);
    }
    if (lane < 4) {
        float di = __ldg(&g_dinv[n]);
        unsigned vn = __ldg(&g_v[n]);
        float4 ws = *(const float4*)&sEW[(vn & 0x7Fu) * HID + lane * 4];
        float4 b  = __ldg((const float4*)b1 + lane);
        float4 h;
        h.x = fmaxf((acc.x + ws.x * di) * di + b.x, 0.0f);   // self loop: dinv^2 exact
        h.y = fmaxf((acc.y + ws.y * di) * di + b.y, 0.0f);
        h.z = fmaxf((acc.z + ws.z * di) * di + b.z, 0.0f);
        h.w = fmaxf((acc.w + ws.w * di) * di + b.w, 0.0f);
        g_h1[n * 4 + lane] = h;
    }
}

// a2[i] = (h1[i] @ W2) * dinv[i]  -> fp16 row (32B)
__global__ __launch_bounds__(256) void k_l2(const float* __restrict__ W2) {
    __shared__ float sW[HID * HID];
    if (threadIdx.x < HID * HID) sW[threadIdx.x] = W2[threadIdx.x];
    __syncthreads();
    int i = blockIdx.x * blockDim.x + threadIdx.x;
    if (i >= N_NODES) return;
    float h[HID];
#pragma unroll
    for (int q = 0; q < 4; q++) {
        float4 v = g_h1[i * 4 + q];
        h[4 * q + 0] = v.x; h[4 * q + 1] = v.y; h[4 * q + 2] = v.z; h[4 * q + 3] = v.w;
    }
    float o[HID];
#pragma unroll
    for (int j = 0; j < HID; j++) o[j] = 0.0f;
#pragma unroll
    for (int k = 0; k < HID; k++)
#pragma unroll
        for (int j = 0; j < HID; j++) o[j] = fmaf(h[k], sW[k * HID + j], o[j]);
    float di = g_dinv[i];
#pragma unroll
    for (int j = 0; j < HID; j++) o[j] *= di;
    uint4 p0, p1;
    p0.x = pack2(o[0], o[1]);   p0.y = pack2(o[2], o[3]);
    p0.z = pack2(o[4], o[5]);   p0.w = pack2(o[6], o[7]);
    p1.x = pack2(o[8], o[9]);   p1.y = pack2(o[10], o[11]);
    p1.z = pack2(o[12], o[13]); p1.w = pack2(o[14], o[15]);
    g_a2h[i * 2 + 0] = p0;
    g_a2h[i * 2 + 1] = p1;
}

// layer-2 gather: warp per node, 2 lanes per edge (16 edges/iter), fp16 rows
__global__ __launch_bounds__(256) void k_gather2(const float* __restrict__ b2) {
    int n = (blockIdx.x * blockDim.x + threadIdx.x) >> 5;
    if (n >= N_NODES) return;
    int lane = threadIdx.x & 31;
    int eq = lane >> 1, fj = lane & 1;      // edge slot / 16B half of the 32B row
    int off = __ldg(&g_off[n]);
    int deg = __ldg(&g_deg[n]);

    float a0=0.f,a1=0.f,a2=0.f,a3=0.f,a4=0.f,a5=0.f,a6=0.f,a7=0.f;
    for (int base = 0; base < deg; base += 16) {
        int e = base + eq;
        if (e < deg) {
            int s = __ldg(&g_csr2[off + e]).x;
            uint4 v = __ldg(&g_a2h[s * 2 + fj]);   // 2 lanes -> one 32B sector
            float2 f;
            f = unpack2(v.x); a0 += f.x; a1 += f.y;
            f = unpack2(v.y); a2 += f.x; a3 += f.y;
            f = unpack2(v.z); a4 += f.x; a5 += f.y;
            f = unpack2(v.w); a6 += f.x; a7 += f.y;
        }
    }
#pragma unroll
    for (int o = 16; o >= 2; o >>= 1) {
        a0 += __shfl_down_sync(0xffffffffu, a0, o);
        a1 += __shfl_down_sync(0xffffffffu, a1, o);
        a2 += __shfl_down_sync(0xffffffffu, a2, o);
        a3 += __shfl_down_sync(0xffffffffu, a3, o);
        a4 += __shfl_down_sync(0xffffffffu, a4, o);
        a5 += __shfl_down_sync(0xffffffffu, a5, o);
        a6 += __shfl_down_sync(0xffffffffu, a6, o);
        a7 += __shfl_down_sync(0xffffffffu, a7, o);
    }
    if (lane < 2) {
        float di = __ldg(&g_dinv[n]);
        uint4 sv = __ldg(&g_a2h[n * 2 + lane]);
        float2 f;
        f = unpack2(sv.x); a0 += f.x; a1 += f.y;
        f = unpack2(sv.y); a2 += f.x; a3 += f.y;
        f = unpack2(sv.z); a4 += f.x; a5 += f.y;
        f = unpack2(sv.w); a6 += f.x; a7 += f.y;
        float4 bA = __ldg((const float4*)b2 + 2 * lane);
        float4 bB = __ldg((const float4*)b2 + 2 * lane + 1);
        float4 o0, o1;
        o0.x = fmaxf(a0 * di + bA.x, 0.0f);
        o0.y = fmaxf(a1 * di + bA.y, 0.0f);
        o0.z = fmaxf(a2 * di + bA.z, 0.0f);
        o0.w = fmaxf(a3 * di + bA.w, 0.0f);
        o1.x = fmaxf(a4 * di + bB.x, 0.0f);
        o1.y = fmaxf(a5 * di + bB.y, 0.0f);
        o1.z = fmaxf(a6 * di + bB.z, 0.0f);
        o1.w = fmaxf(a7 * di + bB.w, 0.0f);
        g_h2[n * 4 + 2 * lane + 0] = o0;
        g_h2[n * 4 + 2 * lane + 1] = o1;
    }
}

// pooling: batch sorted -> warp-uniform segments reduce via shuffles
__global__ __launch_bounds__(256) void k_pool(const int* __restrict__ batch) {
    int i = blockIdx.x * blockDim.x + threadIdx.x;
    int lane = threadIdx.x & 31;
    float h[HID];
    int b = -1;
    if (i < N_NODES) {
        b = batch[i];
#pragma unroll
        for (int q = 0; q < 4; q++) {
            float4 v = g_h2[i * 4 + q];
            h[4*q+0] = v.x; h[4*q+1] = v.y; h[4*q+2] = v.z; h[4*q+3] = v.w;
        }
    } else {
#pragma unroll
        for (int k = 0; k < HID; k++) h[k] = 0.0f;
    }
    int b0 = __shfl_sync(0xffffffffu, b, 0);
    bool uniform = __all_sync(0xffffffffu, b == b0);
    if (uniform && b0 >= 0) {
#pragma unroll
        for (int k = 0; k < HID; k++) {
#pragma unroll
            for (int off = 16; off > 0; off >>= 1)
                h[k] += __shfl_down_sync(0xffffffffu, h[k], off);
        }
        if (lane == 0) {
            float4* p = (float4*)&g_sums[b0 * HID];
#pragma unroll
            for (int q = 0; q < 4; q++)
                red4(p + q, h[4*q], h[4*q+1], h[4*q+2], h[4*q+3]);
            atomicAdd(&g_cnt[b0], 32.0f);
        }
    } else if (b >= 0) {
        float4* p = (float4*)&g_sums[b * HID];
#pragma unroll
        for (int q = 0; q < 4; q++)
            red4(p + q, h[4*q], h[4*q+1], h[4*q+2], h[4*q+3]);
        atomicAdd(&g_cnt[b], 1.0f);
    }
}

__global__ __launch_bounds__(256) void k_final(const float* __restrict__ Wc,
                                               const float* __restrict__ bc,
                                               float* __restrict__ out) {
    int g = blockIdx.x * blockDim.x + threadIdx.x;
    if (g >= N_GRAPHS) return;
    float inv = 1.0f / fmaxf(g_cnt[g], 1.0f);
    float p[HID];
#pragma unroll
    for (int k = 0; k < HID; k++) p[k] = g_sums[g * HID + k] * inv;
#pragma unroll
    for (int j = 0; j < LABELS; j++) {
        float s = __ldg(&bc[j]);
#pragma unroll
        for (int k = 0; k < HID; k++) s = fmaf(p[k], __ldg(&Wc[k * LABELS + j]), s);
        out[g * LABELS + j] = s;
    }
}

// ---------------- launch -----------------------------------------------------
extern "C" void kernel_launch(void* const* d_in, const int* in_sizes, int n_in,
                              void* d_out, int out_size) {
    const int*   x    = (const int*)  d_in[0];
    const int*   ei   = (const int*)  d_in[1];
    const int*   batch= (const int*)  d_in[2];
    const float* emb  = (const float*)d_in[3];
    const float* W1   = (const float*)d_in[4];
    const float* b1   = (const float*)d_in[5];
    const float* W2   = (const float*)d_in[6];
    const float* b2   = (const float*)d_in[7];
    const float* Wc   = (const float*)d_in[8];
    const float* bc   = (const float*)d_in[9];
    float* out = (float*)d_out;

    int E = in_sizes[1] / 2;
    const int* src = ei;
    const int* dst = ei + E;

    int gn = (N_NODES + 255) / 256;
    int ge = (E + 255) / 256;
    int gw = (N_NODES * 32 + 255) / 256;     // warp per node

    k_init     <<<gn, 256>>>();
    k_deg_rank <<<ge, 256>>>(dst, E);
    k_scan1    <<<SCAN_NB, SCAN_BLK>>>();
    k_scan2_ew <<<2, 128>>>(emb, W1);
    k_scan3_v  <<<gn, 256>>>(x);
    k_scatter  <<<ge, 256>>>(src, E);
    k_gather1  <<<gw, 256>>>(b1);
    k_l2       <<<gn, 256>>>(W2);
    k_gather2  <<<gw, 256>>>(b2);
    k_pool     <<<gn, 256>>>(batch);
    k_final    <<<(N_GRAPHS + 255) / 256, 256>>>(Wc, bc, out);
}

// round 12
// speedup vs baseline: 1.0426x; 1.0426x over previous
#include <cuda_runtime.h>
#include <cuda_bf16.h>

#define N_NODES  100000
#define N_EDGES  3200000
#define N_GRAPHS 512
#define HID      16
#define LABELS   10
#define VOCAB    128

#define NB  98          // build blocks (1024 nodes each; 98*1024 >= N_NODES)
#define BT  1024
#define INIT_BLKS 391   // ceil(N_NODES/256) node-init blocks; block INIT_BLKS does EW

// ---------------- scratch (device globals; no allocation allowed) ----------
__device__ int      g_deg   [N_NODES];
__device__ int      g_off   [N_NODES];
__device__ int      g_cursor[N_NODES];
__device__ int      g_bsum  [NB];
__device__ int      g_csr   [N_EDGES];
__device__ float    g_dinv  [N_NODES];
__device__ float4   g_a1    [N_NODES * 4];
__device__ float4   g_h1    [N_NODES * 4];
__device__ float4   g_a2    [N_NODES * 4];
__device__ float4   g_h2    [N_NODES * 4];
__device__ float4   g_EW    [VOCAB * 4];
__device__ float    g_sums  [N_GRAPHS * HID];
__device__ float    g_cnt   [N_GRAPHS];
__device__ unsigned g_barc  [4];

__device__ __forceinline__ void red4(float4* p, float a, float b, float c, float d) {
    asm volatile("red.global.add.v4.f32 [%0], {%1,%2,%3,%4};"
                 :: "l"(p), "f"(a), "f"(b), "f"(c), "f"(d) : "memory");
}
__device__ __forceinline__ void redu(int* p) {
    asm volatile("red.global.add.u32 [%0], %1;" :: "l"(p), "r"(1u) : "memory");
}

// grid barrier: all NB blocks resident -> safe spin
__device__ __forceinline__ void grid_barrier(int slot, unsigned nb) {
    __syncthreads();
    if (threadIdx.x == 0) {
        __threadfence();
        unsigned arrived = atomicAdd(&g_barc[slot], 1u) + 1;
        if (arrived < nb) {
            while (*(volatile unsigned*)&g_barc[slot] < nb) __nanosleep(32);
        }
        __threadfence();
    }
    __syncthreads();
}

// ---------------- init + EW (independent blocks, one launch) ----------------
__global__ __launch_bounds__(256) void k_init_ew(const float* __restrict__ emb,
                                                 const float* __restrict__ W1) {
    int t = threadIdx.x;
    if (blockIdx.x == INIT_BLKS) {            // EW block: EW = emb @ W1
        __shared__ float sW[HID * HID];
        sW[t] = W1[t];                         // 256 threads, 256 weights
        __syncthreads();
        if (t < 128) {
            float h[HID];
#pragma unroll
            for (int k = 0; k < HID; k++) h[k] = emb[t * HID + k];
#pragma unroll
            for (int q = 0; q < 4; q++) {
                float o[4];
#pragma unroll
                for (int jj = 0; jj < 4; jj++) {
                    float s = 0.0f;
#pragma unroll
                    for (int k = 0; k < HID; k++) s = fmaf(h[k], sW[k * HID + 4 * q + jj], s);
                    o[jj] = s;
                }
                g_EW[t * 4 + q] = make_float4(o[0], o[1], o[2], o[3]);
            }
        }
        return;
    }
    int i = blockIdx.x * 256 + t;
    if (i < N_NODES) g_deg[i] = 0;
    if (i < N_GRAPHS * HID) g_sums[i] = 0.0f;
    if (i < N_GRAPHS) g_cnt[i] = 0.0f;
    if (i < 4) g_barc[i] = 0u;
}

// ---------------- fused build: deg -> scan -> offsets/dinv/a1 -> scatter ----
__global__ __launch_bounds__(BT) void k_build(const int* __restrict__ src,
                                              const int* __restrict__ dst,
                                              const int* __restrict__ x, int E) {
    int tid = threadIdx.x, bid = blockIdx.x;
    int lane = tid & 31, wid = tid >> 5;

    // phase A: degree histogram (no-return reds, coalesced grid-stride)
    for (int e = bid * BT + tid; e < E; e += NB * BT) redu(&g_deg[dst[e]]);
    grid_barrier(0, NB);

    // phase B: per-block shfl scan of this block's 1024 degrees
    __shared__ int wtot[32];
    __shared__ int sm[128];
    __shared__ int s_base;
    int gid = bid * BT + tid;
    int v = (gid < N_NODES) ? g_deg[gid] : 0;
    int xc = v;
#pragma unroll
    for (int o = 1; o < 32; o <<= 1) {
        int t2 = __shfl_up_sync(0xffffffffu, xc, o);
        if (lane >= o) xc += t2;
    }
    if (lane == 31) wtot[wid] = xc;
    __syncthreads();
    if (tid < 32) {
        int w = wtot[tid];
        int y = w;
#pragma unroll
        for (int o = 1; o < 32; o <<= 1) {
            int t2 = __shfl_up_sync(0xffffffffu, y, o);
            if (tid >= o) y += t2;
        }
        wtot[tid] = y - w;                    // exclusive warp base
        if (tid == 31) g_bsum[bid] = y;       // block total
    }
    __syncthreads();
    int local_ex = xc - v + wtot[wid];
    grid_barrier(1, NB);

    // phase C: every block redundantly scans the 98 block totals (no 3rd hop)
    if (tid < 128) sm[tid] = (tid < NB) ? g_bsum[tid] : 0;
    __syncthreads();
#pragma unroll
    for (int off = 1; off < 128; off <<= 1) {
        int u = (tid >= off && tid < 128) ? sm[tid - off] : 0;
        __syncthreads();
        if (tid < 128) sm[tid] += u;
        __syncthreads();
    }
    if (tid == 0) s_base = sm[bid] - g_bsum[bid];   // exclusive base for this block
    __syncthreads();
    int base = s_base;

    // phase D: offsets, cursors, dinv, a1 = EW[x]*dinv
    if (gid < N_NODES) {
        int o = base + local_ex;
        g_off[gid] = o;
        g_cursor[gid] = o;
        float di = rsqrtf((float)v + 1.0f);         // +1 self loop
        g_dinv[gid] = di;
        const float4* r = &g_EW[x[gid] * 4];
#pragma unroll
        for (int q = 0; q < 4; q++) {
            float4 w = r[q];
            g_a1[gid * 4 + q] = make_float4(w.x * di, w.y * di, w.z * di, w.w * di);
        }
    }
    grid_barrier(2, NB);

    // phase E: scatter edges into CSR via cursor atomics
    for (int e = bid * BT + tid; e < E; e += NB * BT) {
        int pos = atomicAdd(&g_cursor[dst[e]], 1);
        g_csr[pos] = src[e];
    }
}

// ---------------- layer-1 gather (warp/node, 4 lanes per edge) --------------
__global__ __launch_bounds__(256) void k_gather1(const float* __restrict__ b1) {
    int n = (blockIdx.x * blockDim.x + threadIdx.x) >> 5;
    if (n >= N_NODES) return;
    int lane = threadIdx.x & 31;
    int eq = lane >> 2, fj = lane & 3;
    int off = __ldg(&g_off[n]);
    int deg = __ldg(&g_deg[n]);

    float4 acc = make_float4(0.f, 0.f, 0.f, 0.f);
    for (int base = 0; base < deg; base += 8) {
        int e = base + eq;
        if (e < deg) {
            int s = __ldg(&g_csr[off + e]);
            float4 v = __ldg(&g_a1[s * 4 + fj]);
            acc.x += v.x; acc.y += v.y; acc.z += v.z; acc.w += v.w;
        }
    }
#pragma unroll
    for (int o = 16; o >= 4; o >>= 1) {
        acc.x += __shfl_down_sync(0xffffffffu, acc.x, o);
        acc.y += __shfl_down_sync(0xffffffffu, acc.y, o);
        acc.z += __shfl_down_sync(0xffffffffu, acc.z, o);
        acc.w += __shfl_down_sync(0xffffffffu, acc.w, o);
    }
    if (lane < 4) {
        float di = __ldg(&g_dinv[n]);
        float4 self = __ldg(&g_a1[n * 4 + lane]);
        float4 b = __ldg((const float4*)b1 + lane);
        float4 h;
        h.x = fmaxf((acc.x + self.x) * di + b.x, 0.0f);
        h.y = fmaxf((acc.y + self.y) * di + b.y, 0.0f);
        h.z = fmaxf((acc.z + self.z) * di + b.z, 0.0f);
        h.w = fmaxf((acc.w + self.w) * di + b.w, 0.0f);
        g_h1[n * 4 + lane] = h;
    }
}

// a2[i] = (h1[i] @ W2) * dinv[i]
__global__ __launch_bounds__(256) void k_l2(const float* __restrict__ W2) {
    __shared__ float sW[HID * HID];
    if (threadIdx.x < HID * HID) sW[threadIdx.x] = W2[threadIdx.x];
    __syncthreads();
    int i = blockIdx.x * blockDim.x + threadIdx.x;
    if (i >= N_NODES) return;
    float h[HID];
#pragma unroll
    for (int q = 0; q < 4; q++) {
        float4 v = g_h1[i * 4 + q];
        h[4 * q + 0] = v.x; h[4 * q + 1] = v.y; h[4 * q + 2] = v.z; h[4 * q + 3] = v.w;
    }
    float o[HID];
#pragma unroll
    for (int j = 0; j < HID; j++) o[j] = 0.0f;
#pragma unroll
    for (int k = 0; k < HID; k++)
#pragma unroll
        for (int j = 0; j < HID; j++) o[j] = fmaf(h[k], sW[k * HID + j], o[j]);
    float di = g_dinv[i];
#pragma unroll
    for (int q = 0; q < 4; q++)
        g_a2[i * 4 + q] = make_float4(o[4*q]*di, o[4*q+1]*di, o[4*q+2]*di, o[4*q+3]*di);
}

// ---------------- layer-2 gather ---------------------------------------------
__global__ __launch_bounds__(256) void k_gather2(const float* __restrict__ b2) {
    int n = (blockIdx.x * blockDim.x + threadIdx.x) >> 5;
    if (n >= N_NODES) return;
    int lane = threadIdx.x & 31;
    int eq = lane >> 2, fj = lane & 3;
    int off = __ldg(&g_off[n]);
    int deg = __ldg(&g_deg[n]);

    float4 acc = make_float4(0.f, 0.f, 0.f, 0.f);
    for (int base = 0; base < deg; base += 8) {
        int e = base + eq;
        if (e < deg) {
            int s = __ldg(&g_csr[off + e]);
            float4 v = __ldg(&g_a2[s * 4 + fj]);
            acc.x += v.x; acc.y += v.y; acc.z += v.z; acc.w += v.w;
        }
    }
#pragma unroll
    for (int o = 16; o >= 4; o >>= 1) {
        acc.x += __shfl_down_sync(0xffffffffu, acc.x, o);
        acc.y += __shfl_down_sync(0xffffffffu, acc.y, o);
        acc.z += __shfl_down_sync(0xffffffffu, acc.z, o);
        acc.w += __shfl_down_sync(0xffffffffu, acc.w, o);
    }
    if (lane < 4) {
        float di = __ldg(&g_dinv[n]);
        float4 self = __ldg(&g_a2[n * 4 + lane]);
        float4 b = __ldg((const float4*)b2 + lane);
        float4 o;
        o.x = fmaxf((acc.x + self.x) * di + b.x, 0.0f);
        o.y = fmaxf((acc.y + self.y) * di + b.y, 0.0f);
        o.z = fmaxf((acc.z + self.z) * di + b.z, 0.0f);
        o.w = fmaxf((acc.w + self.w) * di + b.w, 0.0f);
        g_h2[n * 4 + lane] = o;
    }
}

// pooling: batch sorted -> warp-uniform segments reduce via shuffles
__global__ __launch_bounds__(256) void k_pool(const int* __restrict__ batch) {
    int i = blockIdx.x * blockDim.x + threadIdx.x;
    int lane = threadIdx.x & 31;
    float h[HID];
    int b = -1;
    if (i < N_NODES) {
        b = batch[i];
#pragma unroll
        for (int q = 0; q < 4; q++) {
            float4 v = g_h2[i * 4 + q];
            h[4*q+0] = v.x; h[4*q+1] = v.y; h[4*q+2] = v.z; h[4*q+3] = v.w;
        }
    } else {
#pragma unroll
        for (int k = 0; k < HID; k++) h[k] = 0.0f;
    }
    int b0 = __shfl_sync(0xffffffffu, b, 0);
    bool uniform = __all_sync(0xffffffffu, b == b0);
    if (uniform && b0 >= 0) {
#pragma unroll
        for (int k = 0; k < HID; k++) {
#pragma unroll
            for (int off = 16; off > 0; off >>= 1)
                h[k] += __shfl_down_sync(0xffffffffu, h[k], off);
        }
        if (lane == 0) {
            float4* p = (float4*)&g_sums[b0 * HID];
#pragma unroll
            for (int q = 0; q < 4; q++)
                red4(p + q, h[4*q], h[4*q+1], h[4*q+2], h[4*q+3]);
            atomicAdd(&g_cnt[b0], 32.0f);
        }
    } else if (b >= 0) {
        float4* p = (float4*)&g_sums[b * HID];
#pragma unroll
        for (int q = 0; q < 4; q++)
            red4(p + q, h[4*q], h[4*q+1], h[4*q+2], h[4*q+3]);
        atomicAdd(&g_cnt[b], 1.0f);
    }
}

__global__ __launch_bounds__(256) void k_final(const float* __restrict__ Wc,
                                               const float* __restrict__ bc,
                                               float* __restrict__ out) {
    int g = blockIdx.x * blockDim.x + threadIdx.x;
    if (g >= N_GRAPHS) return;
    float inv = 1.0f / fmaxf(g_cnt[g], 1.0f);
    float p[HID];
#pragma unroll
    for (int k = 0; k < HID; k++) p[k] = g_sums[g * HID + k] * inv;
#pragma unroll
    for (int j = 0; j < LABELS; j++) {
        float s = __ldg(&bc[j]);
#pragma unroll
        for (int k = 0; k < HID; k++) s = fmaf(p[k], __ldg(&Wc[k * LABELS + j]), s);
        out[g * LABELS + j] = s;
    }
}

// ---------------- launch -----------------------------------------------------
extern "C" void kernel_launch(void* const* d_in, const int* in_sizes, int n_in,
                              void* d_out, int out_size) {
    const int*   x    = (const int*)  d_in[0];
    const int*   ei   = (const int*)  d_in[1];
    const int*   batch= (const int*)  d_in[2];
    const float* emb  = (const float*)d_in[3];
    const float* W1   = (const float*)d_in[4];
    const float* b1   = (const float*)d_in[5];
    const float* W2   = (const float*)d_in[6];
    const float* b2   = (const float*)d_in[7];
    const float* Wc   = (const float*)d_in[8];
    const float* bc   = (const float*)d_in[9];
    float* out = (float*)d_out;

    int E = in_sizes[1] / 2;
    const int* src = ei;
    const int* dst = ei + E;

    int gn = (N_NODES + 255) / 256;
    int gw = (N_NODES * 32 + 255) / 256;     // warp per node

    k_init_ew <<<INIT_BLKS + 1, 256>>>(emb, W1);
    k_build   <<<NB, BT>>>(src, dst, x, E);
    k_gather1 <<<gw, 256>>>(b1);
    k_l2      <<<gn, 256>>>(W2);
    k_gather2 <<<gw, 256>>>(b2);
    k_pool    <<<gn, 256>>>(batch);
    k_final   <<<(N_GRAPHS + 255) / 256, 256>>>(Wc, bc, out);
}